// round 7
// baseline (speedup 1.0000x reference)
#include <cuda_runtime.h>
#include <cuda_bf16.h>
#include <stdint.h>

// out_f32[4096, 4096] = bf16round( x_bf16[4096,4096] @ W_bf16[4096,4096]^T + bias )
// NOTE: d_out is FLOAT32 (harness stores the bf16 reference as f32).
#define TOKENS 4096
#define KDIM   4096
#define NDIM   4096

// GEMM tiling: 128x128 CTA tile, BK=64, 8 warps (4 m x 2 n), warp tile 32x64
#define BM 128
#define BN 128
#define BK 64
#define NUM_KT (KDIM / BK)        // 64
#define STAGES 3
#define STAGE_BYTES 16384         // 128 rows x 128B per operand per stage
#define SMEM_TOTAL (STAGES * 2 * STAGE_BYTES)   // 98304 -> 2 CTAs/SM

// Scratch: pre-converted bf16 operands (__device__ globals; no allocs)
__device__ __align__(256) __nv_bfloat16 g_x[(size_t)TOKENS * KDIM];
__device__ __align__(256) __nv_bfloat16 g_w[(size_t)NDIM * KDIM];

// ---------------- helpers ----------------
static __device__ __forceinline__ uint32_t smem_u32(const void* p) {
    uint32_t a;
    asm("{ .reg .u64 t; cvta.to.shared.u64 t, %1; cvt.u32.u64 %0, t; }" : "=r"(a) : "l"(p));
    return a;
}
static __device__ __forceinline__ void cp_async16(uint32_t smem_dst, uint64_t gsrc) {
    asm volatile("cp.async.cg.shared.global [%0], [%1], 16;"
                 :: "r"(smem_dst), "l"(gsrc) : "memory");
}

// ---------------- conversion kernels ----------------
__global__ void cvt_x_kernel(const float* __restrict__ x) {
    const size_t total = (size_t)TOKENS * KDIM / 4;
    const size_t stride = (size_t)gridDim.x * blockDim.x;
    for (size_t i = (size_t)blockIdx.x * blockDim.x + threadIdx.x; i < total; i += stride) {
        float4 v = reinterpret_cast<const float4*>(x)[i];
        __nv_bfloat162 lo, hi;
        lo.x = __float2bfloat16(v.x); lo.y = __float2bfloat16(v.y);
        hi.x = __float2bfloat16(v.z); hi.y = __float2bfloat16(v.w);
        reinterpret_cast<__nv_bfloat162*>(g_x)[2 * i]     = lo;
        reinterpret_cast<__nv_bfloat162*>(g_x)[2 * i + 1] = hi;
    }
}
__global__ void cvt_w_kernel(const float* __restrict__ w, const float* __restrict__ scale) {
    const size_t total = (size_t)NDIM * KDIM / 4;
    const size_t stride = (size_t)gridDim.x * blockDim.x;
    for (size_t i = (size_t)blockIdx.x * blockDim.x + threadIdx.x; i < total; i += stride) {
        int row = (int)(i >> 10);  // (i*4) / 4096
        // reference: bf16(fp8_val) * bf16(scale) in bf16; fp8 vals exact in f32,
        // so fp32 multiply then single bf16 round matches.
        float s = __bfloat162float(__float2bfloat16(__ldg(&scale[row])));
        float4 v = reinterpret_cast<const float4*>(w)[i];
        __nv_bfloat162 lo, hi;
        lo.x = __float2bfloat16(v.x * s); lo.y = __float2bfloat16(v.y * s);
        hi.x = __float2bfloat16(v.z * s); hi.y = __float2bfloat16(v.w * s);
        reinterpret_cast<__nv_bfloat162*>(g_w)[2 * i]     = lo;
        reinterpret_cast<__nv_bfloat162*>(g_w)[2 * i + 1] = hi;
    }
}

// ---------------- mma.sync bf16 GEMM (compute_103-safe tensor path) ----------------
__global__ void __launch_bounds__(256, 2)
fp8lin_gemm(const float* __restrict__ bias, float* __restrict__ out) {
    extern __shared__ char smem[];
    const uint32_t sb = smem_u32(smem);
    const int tid = threadIdx.x;
    const int wid = tid >> 5, lane = tid & 31;
    const int wm = wid >> 1, wn = wid & 1;         // 4x2 warp grid
    const int m0 = blockIdx.y * BM, n0 = blockIdx.x * BN;

    uint64_t gA, gB;
    {
        const void* pa = g_x + (size_t)m0 * KDIM;
        const void* pb = g_w + (size_t)n0 * KDIM;
        asm("cvta.to.global.u64 %0, %1;" : "=l"(gA) : "l"(pa));
        asm("cvta.to.global.u64 %0, %1;" : "=l"(gB) : "l"(pb));
    }

    // cp.async stage loader: 1024 16B chunks per operand, 4 per thread.
    // SMEM rows are 128B with Swizzle<3,4,3>: chunk ^= (row&7), on bits [6:4].
    auto load_stage = [&](int s, int kt) {
        const uint32_t sA = sb + (uint32_t)s * STAGE_BYTES;
        const uint32_t sB = sb + (uint32_t)(STAGES + s) * STAGE_BYTES;
        const uint64_t koff = (uint64_t)kt * (BK * 2);   // 128B per K-chunk
        #pragma unroll
        for (int it = 0; it < 4; ++it) {
            int idx = tid + it * 256;
            int row = idx >> 3, c = idx & 7;
            uint32_t so = ((uint32_t)row << 7) | (uint32_t)((c << 4) ^ ((row & 7) << 4));
            uint64_t go = (uint64_t)row * (KDIM * 2) + koff + (uint64_t)(c << 4);
            cp_async16(sA + so, gA + go);
            cp_async16(sB + so, gB + go);
        }
        asm volatile("cp.async.commit_group;" ::: "memory");
    };

    // ldmatrix per-thread address components.
    const int j = lane >> 3, i8 = lane & 7;
    // A m16k16 tile: matrices {rows0-7 klo, rows8-15 klo, rows0-7 khi, rows8-15 khi}
    uint32_t aP[2], aX[2];
    #pragma unroll
    for (int mt = 0; mt < 2; ++mt) {
        int r = wm * 32 + mt * 16 + (j & 1) * 8 + i8;
        aP[mt] = (uint32_t)r << 7;
        aX[mt] = (uint32_t)((r & 7) << 4);
    }
    const uint32_t aK = (uint32_t)((j >> 1) << 4);
    // B n16k16 group: matrices {n0-7 klo, n0-7 khi, n8-15 klo, n8-15 khi}
    uint32_t bP[4], bX[4];
    #pragma unroll
    for (int g = 0; g < 4; ++g) {
        int r = wn * 64 + g * 16 + ((j >> 1) & 1) * 8 + i8;
        bP[g] = (uint32_t)r << 7;
        bX[g] = (uint32_t)((r & 7) << 4);
    }
    const uint32_t bK = (uint32_t)((j & 1) << 4);

    float acc[2][8][4];
    #pragma unroll
    for (int mt = 0; mt < 2; ++mt)
        #pragma unroll
        for (int nt = 0; nt < 8; ++nt)
            #pragma unroll
            for (int q = 0; q < 4; ++q) acc[mt][nt][q] = 0.0f;

    load_stage(0, 0);
    load_stage(1, 1);

    for (int kt = 0; kt < NUM_KT; ++kt) {
        if (kt + 2 < NUM_KT) {
            load_stage((kt + 2) % STAGES, kt + 2);
            asm volatile("cp.async.wait_group 2;" ::: "memory");
        } else if (kt + 2 == NUM_KT) {
            asm volatile("cp.async.wait_group 1;" ::: "memory");
        } else {
            asm volatile("cp.async.wait_group 0;" ::: "memory");
        }
        __syncthreads();

        const int s = kt % STAGES;
        const uint32_t sA = sb + (uint32_t)s * STAGE_BYTES;
        const uint32_t sB = sb + (uint32_t)(STAGES + s) * STAGE_BYTES;

        #pragma unroll
        for (int ks = 0; ks < 4; ++ks) {
            const uint32_t kb = (uint32_t)(ks << 5);
            uint32_t a[2][4];
            #pragma unroll
            for (int mt = 0; mt < 2; ++mt) {
                uint32_t addr = sA + aP[mt] + ((kb + aK) ^ aX[mt]);
                asm volatile("ldmatrix.sync.aligned.m8n8.x4.shared.b16 {%0,%1,%2,%3}, [%4];"
                             : "=r"(a[mt][0]), "=r"(a[mt][1]), "=r"(a[mt][2]), "=r"(a[mt][3])
                             : "r"(addr));
            }
            uint32_t b[4][4];
            #pragma unroll
            for (int g = 0; g < 4; ++g) {
                uint32_t addr = sB + bP[g] + ((kb + bK) ^ bX[g]);
                asm volatile("ldmatrix.sync.aligned.m8n8.x4.shared.b16 {%0,%1,%2,%3}, [%4];"
                             : "=r"(b[g][0]), "=r"(b[g][1]), "=r"(b[g][2]), "=r"(b[g][3])
                             : "r"(addr));
            }
            #pragma unroll
            for (int mt = 0; mt < 2; ++mt) {
                #pragma unroll
                for (int nt = 0; nt < 8; ++nt) {
                    const uint32_t b0 = b[nt >> 1][(nt & 1) * 2];
                    const uint32_t b1 = b[nt >> 1][(nt & 1) * 2 + 1];
                    asm volatile(
                        "mma.sync.aligned.m16n8k16.row.col.f32.bf16.bf16.f32 "
                        "{%0,%1,%2,%3}, {%4,%5,%6,%7}, {%8,%9}, {%0,%1,%2,%3};"
                        : "+f"(acc[mt][nt][0]), "+f"(acc[mt][nt][1]),
                          "+f"(acc[mt][nt][2]), "+f"(acc[mt][nt][3])
                        : "r"(a[mt][0]), "r"(a[mt][1]), "r"(a[mt][2]), "r"(a[mt][3]),
                          "r"(b0), "r"(b1));
                }
            }
        }
        __syncthreads();
    }

    // ---- epilogue: f32 acc -> bf16 round, + bf16 bias (reference bf16 math),
    // ---- then store as FLOAT32 (d_out dtype is f32).
    const int g4 = lane >> 2, tig = lane & 3;
    #pragma unroll
    for (int nt = 0; nt < 8; ++nt) {
        const int col = n0 + wn * 64 + nt * 8 + tig * 2;
        const __nv_bfloat16 bz0 = __float2bfloat16(__ldg(&bias[col]));
        const __nv_bfloat16 bz1 = __float2bfloat16(__ldg(&bias[col + 1]));
        #pragma unroll
        for (int mt = 0; mt < 2; ++mt) {
            const int r0 = m0 + wm * 32 + mt * 16 + g4;
            float2 v0, v1;
            v0.x = __bfloat162float(__hadd(__float2bfloat16(acc[mt][nt][0]), bz0));
            v0.y = __bfloat162float(__hadd(__float2bfloat16(acc[mt][nt][1]), bz1));
            v1.x = __bfloat162float(__hadd(__float2bfloat16(acc[mt][nt][2]), bz0));
            v1.y = __bfloat162float(__hadd(__float2bfloat16(acc[mt][nt][3]), bz1));
            *reinterpret_cast<float2*>(out + (size_t)r0 * NDIM + col) = v0;
            *reinterpret_cast<float2*>(out + (size_t)(r0 + 8) * NDIM + col) = v1;
        }
    }
}

// ---------------- launch ----------------
extern "C" void kernel_launch(void* const* d_in, const int* in_sizes, int n_in,
                              void* d_out, int out_size) {
    const float* x     = (const float*)d_in[0];   // [2,2048,4096] f32
    const float* w     = (const float*)d_in[1];   // [4096,4096] f32 (fp8-representable)
    const float* scale = (const float*)d_in[2];   // [4096,1] f32
    const float* bias  = (const float*)d_in[3];   // [4096] f32
    float* out         = (float*)d_out;           // [2,2048,4096] f32 (bf16 values widened)

    cudaFuncSetAttribute(fp8lin_gemm, cudaFuncAttributeMaxDynamicSharedMemorySize, SMEM_TOTAL);

    cvt_x_kernel<<<2048, 256>>>(x);
    cvt_w_kernel<<<2048, 256>>>(w, scale);

    dim3 grid(NDIM / BN, TOKENS / BM);  // (32, 32) = 1024 CTAs
    fp8lin_gemm<<<grid, 256, SMEM_TOTAL>>>(bias, out);
}